// round 11
// baseline (speedup 1.0000x reference)
#include <cuda_runtime.h>
#include <cuda_bf16.h>

// CliffordLayerNorm — R11: combine the two best measured axes.
// Grid-stride with exactly TWO groups per warp (4096 CTAs) at occ 4
// (64-reg cap). R5 showed 2 grp/warp > 1 at occ 3; R7 showed occ 4 > 3 at
// 1 grp/warp; this is the untested corner of the measured-favorable plane.
//
// Structure otherwise identical to the converged R7 kernel:
//  - 8 lanes per MV; warp covers one group of 4 MVs (4KB) per iteration.
//  - Pass 1 streams x into grade-relative sum/sumsq accumulators.
//  - 3-step shuffle-XOR grade-polynomial butterfly (6->7->8->9).
//  - var = E[x^2] - mean^2; affine collapsed to one FMA per element.
//  - Pass 2 reloads x via ld.global.nc (L1-resident), FMA, store.

#define NG 9
#define CEPS 1e-5f

__global__ void __launch_bounds__(256, 4)
clifford_ln_kernel(const float* __restrict__ x,
                   const float* __restrict__ weight,
                   const float* __restrict__ bias,
                   float* __restrict__ out,
                   int num_groups)   // groups of 1024 floats (4 MVs)
{
    const int lane = threadIdx.x & 31;
    const int wid_global = blockIdx.x * (blockDim.x >> 5) + (threadIdx.x >> 5);
    const int nwarps = gridDim.x * (blockDim.x >> 5);
    const int sub = lane & 7;     // covers element bits 2,3,4
    const int mv  = lane >> 3;    // which of 4 MVs in the group
    const int p   = __popc(sub);  // relative grade base, 0..3

    // per-grade reciprocal counts C(8,g) = 1,8,28,56,70,56,28,8,1
    const float rc[NG] = {1.0f, 1.0f/8.0f, 1.0f/28.0f, 1.0f/56.0f, 1.0f/70.0f,
                          1.0f/56.0f, 1.0f/28.0f, 1.0f/8.0f, 1.0f};

#pragma unroll 1
    for (int grp = wid_global; grp < num_groups; grp += nwarps) {
        const float4* __restrict__ xin =
            reinterpret_cast<const float4*>(x) + (size_t)grp * 256 + mv * 64 + sub;
        float4* __restrict__ xout =
            reinterpret_cast<float4*>(out) + (size_t)grp * 256 + mv * 64 + sub;

        // ---- Pass 1: stream loads into grade-relative partial sums ----
        // t = popc(k)+popc(j) in 0..5.
        float S[NG], Q[NG];
#pragma unroll
        for (int t = 0; t < NG; ++t) { S[t] = 0.0f; Q[t] = 0.0f; }
#pragma unroll
        for (int k = 0; k < 8; ++k) {
            const int pk = __popc(k);          // compile-time after unroll
            const float4 v = xin[k * 8];
            S[pk + 0] += v.x;  Q[pk + 0] = fmaf(v.x, v.x, Q[pk + 0]);
            S[pk + 1] += v.y;  Q[pk + 1] = fmaf(v.y, v.y, Q[pk + 1]);
            S[pk + 1] += v.z;  Q[pk + 1] = fmaf(v.z, v.z, Q[pk + 1]);
            S[pk + 2] += v.w;  Q[pk + 2] = fmaf(v.w, v.w, Q[pk + 2]);
        }

        // ---- Butterfly merge over lane bits 0..2 (sub). 6 -> 7 -> 8 -> 9 ----
#pragma unroll
        for (int b = 0; b < 3; ++b) {
            const int n = 6 + b;               // current valid length
            const bool up = (sub >> b) & 1;
            float Sp[NG], Qp[NG];
#pragma unroll
            for (int t = 0; t < NG; ++t) {
                if (t < n) {
                    Sp[t] = __shfl_xor_sync(0xffffffffu, S[t], 1 << b);
                    Qp[t] = __shfl_xor_sync(0xffffffffu, Q[t], 1 << b);
                }
            }
            float Sn[NG], Qn[NG];
#pragma unroll
            for (int t = 0; t < NG; ++t) {
                if (t <= n) {
                    float lo_s = (t < n) ? (up ? Sp[t] : S[t]) : 0.0f;
                    float hi_s = (t > 0) ? (up ? S[t - 1] : Sp[t - 1]) : 0.0f;
                    Sn[t] = lo_s + hi_s;
                    float lo_q = (t < n) ? (up ? Qp[t] : Q[t]) : 0.0f;
                    float hi_q = (t > 0) ? (up ? Q[t - 1] : Qp[t - 1]) : 0.0f;
                    Qn[t] = lo_q + hi_q;
                }
            }
#pragma unroll
            for (int t = 0; t < NG; ++t) {
                if (t <= n) { S[t] = Sn[t]; Q[t] = Qn[t]; }
            }
        }

        // ---- Per-grade affine coefficients; compress to this lane's 6 ----
        float At[6], Bt[6];
#pragma unroll
        for (int g = 0; g < NG; ++g) {
            float m   = S[g] * rc[g];
            float var = fmaf(Q[g], rc[g], -m * m);
            float inv = rsqrtf(var + CEPS);
            float a   = inv * __ldg(weight + g);
            float b   = fmaf(-m, a, __ldg(bias + g));
            // lane needs grades p..p+5 -> slot t = g - p
#pragma unroll
            for (int t = 0; t < 6; ++t) {
                if (g - t == 0 ? (p == 0) : (g - t == 1 ? (p == 1) :
                    (g - t == 2 ? (p == 2) : (g - t == 3 && p == 3)))) {
                    At[t] = a; Bt[t] = b;
                }
            }
        }

        // ---- Pass 2: reload x (L1 hit), FMA, plain store ----
        // asm volatile loads prevent CSE with pass-1 loads.
#pragma unroll
        for (int k = 0; k < 8; ++k) {
            const int pk = __popc(k);
            const float4* addr = xin + k * 8;
            float vx, vy, vz, vw;
            asm volatile("ld.global.nc.v4.f32 {%0,%1,%2,%3}, [%4];"
                         : "=f"(vx), "=f"(vy), "=f"(vz), "=f"(vw)
                         : "l"(addr));
            float4 o;
            o.x = fmaf(vx, At[pk + 0], Bt[pk + 0]);
            o.y = fmaf(vy, At[pk + 1], Bt[pk + 1]);
            o.z = fmaf(vz, At[pk + 1], Bt[pk + 1]);
            o.w = fmaf(vw, At[pk + 2], Bt[pk + 2]);
            xout[k * 8] = o;
        }
    }
}

extern "C" void kernel_launch(void* const* d_in, const int* in_sizes, int n_in,
                              void* d_out, int out_size)
{
    const float* x      = (const float*)d_in[0];
    const float* weight = (const float*)d_in[1];
    const float* bias   = (const float*)d_in[2];
    float* out          = (float*)d_out;

    const int num_groups = in_sizes[0] / 1024;   // 4 MVs (1024 floats) per group

    // Two groups per warp (grid-stride, 2 iterations), 8 warps per CTA.
    const int threads = 256;
    int warps_needed = (num_groups + 1) / 2;
    int blocks = (warps_needed + 7) / 8;        // 65536 groups -> 4096 CTAs
    clifford_ln_kernel<<<blocks, threads>>>(x, weight, bias, out, num_groups);
}

// round 12
// speedup vs baseline: 1.0394x; 1.0394x over previous
#include <cuda_runtime.h>
#include <cuda_bf16.h>

// CliffordLayerNorm — R12: probe the block-size trend endpoint.
// 512-thread CTAs (16 warps), __launch_bounds__(512, 2): same 64-reg cap and
// 32 warps/SM as the converged R7 kernel, but half the CTA count (4096).
// Measured trend: 128thr=77.3, 256thr=75.1 (ncu us) -> larger CTAs amortize
// per-CTA overhead; this tests 512.
//
// Structure identical to R7 (measured optimal):
//  - 8 lanes per MV; warp covers one group of 4 MVs (4KB); ONE group per
//    warp, no loop (CTA exit pipelines the next CTA's loads via CLC).
//  - Pass 1 streams x into grade-relative sum/sumsq accumulators.
//  - 3-step shuffle-XOR grade-polynomial butterfly (6->7->8->9).
//  - var = E[x^2] - mean^2; affine collapsed to one FMA per element.
//  - Pass 2 reloads x via ld.global.nc (L1-resident), FMA, store.

#define NG 9
#define CEPS 1e-5f

__global__ void __launch_bounds__(512, 2)
clifford_ln_kernel(const float* __restrict__ x,
                   const float* __restrict__ weight,
                   const float* __restrict__ bias,
                   float* __restrict__ out,
                   int num_groups)   // groups of 1024 floats (4 MVs)
{
    const int lane = threadIdx.x & 31;
    const int grp = blockIdx.x * (blockDim.x >> 5) + (threadIdx.x >> 5);
    if (grp >= num_groups) return;

    const int sub = lane & 7;     // covers element bits 2,3,4
    const int mv  = lane >> 3;    // which of 4 MVs in the group
    const int p   = __popc(sub);  // relative grade base, 0..3

    // per-grade reciprocal counts C(8,g) = 1,8,28,56,70,56,28,8,1
    const float rc[NG] = {1.0f, 1.0f/8.0f, 1.0f/28.0f, 1.0f/56.0f, 1.0f/70.0f,
                          1.0f/56.0f, 1.0f/28.0f, 1.0f/8.0f, 1.0f};

    const float4* __restrict__ xin =
        reinterpret_cast<const float4*>(x) + (size_t)grp * 256 + mv * 64 + sub;
    float4* __restrict__ xout =
        reinterpret_cast<float4*>(out) + (size_t)grp * 256 + mv * 64 + sub;

    // ---- Pass 1: stream loads into grade-relative partial sums ----
    // t = popc(k)+popc(j) in 0..5.
    float S[NG], Q[NG];
#pragma unroll
    for (int t = 0; t < NG; ++t) { S[t] = 0.0f; Q[t] = 0.0f; }
#pragma unroll
    for (int k = 0; k < 8; ++k) {
        const int pk = __popc(k);          // compile-time after unroll
        const float4 v = xin[k * 8];
        S[pk + 0] += v.x;  Q[pk + 0] = fmaf(v.x, v.x, Q[pk + 0]);
        S[pk + 1] += v.y;  Q[pk + 1] = fmaf(v.y, v.y, Q[pk + 1]);
        S[pk + 1] += v.z;  Q[pk + 1] = fmaf(v.z, v.z, Q[pk + 1]);
        S[pk + 2] += v.w;  Q[pk + 2] = fmaf(v.w, v.w, Q[pk + 2]);
    }

    // ---- Butterfly merge over lane bits 0..2 (sub). 6 -> 7 -> 8 -> 9 ----
#pragma unroll
    for (int b = 0; b < 3; ++b) {
        const int n = 6 + b;               // current valid length
        const bool up = (sub >> b) & 1;
        float Sp[NG], Qp[NG];
#pragma unroll
        for (int t = 0; t < NG; ++t) {
            if (t < n) {
                Sp[t] = __shfl_xor_sync(0xffffffffu, S[t], 1 << b);
                Qp[t] = __shfl_xor_sync(0xffffffffu, Q[t], 1 << b);
            }
        }
        float Sn[NG], Qn[NG];
#pragma unroll
        for (int t = 0; t < NG; ++t) {
            if (t <= n) {
                float lo_s = (t < n) ? (up ? Sp[t] : S[t]) : 0.0f;
                float hi_s = (t > 0) ? (up ? S[t - 1] : Sp[t - 1]) : 0.0f;
                Sn[t] = lo_s + hi_s;
                float lo_q = (t < n) ? (up ? Qp[t] : Q[t]) : 0.0f;
                float hi_q = (t > 0) ? (up ? Q[t - 1] : Qp[t - 1]) : 0.0f;
                Qn[t] = lo_q + hi_q;
            }
        }
#pragma unroll
        for (int t = 0; t < NG; ++t) {
            if (t <= n) { S[t] = Sn[t]; Q[t] = Qn[t]; }
        }
    }

    // ---- Per-grade affine coefficients; compress to this lane's 6 ----
    float At[6], Bt[6];
#pragma unroll
    for (int g = 0; g < NG; ++g) {
        float m   = S[g] * rc[g];
        float var = fmaf(Q[g], rc[g], -m * m);
        float inv = rsqrtf(var + CEPS);
        float a   = inv * __ldg(weight + g);
        float b   = fmaf(-m, a, __ldg(bias + g));
        // lane needs grades p..p+5 -> slot t = g - p
#pragma unroll
        for (int t = 0; t < 6; ++t) {
            if (g - t == 0 ? (p == 0) : (g - t == 1 ? (p == 1) :
                (g - t == 2 ? (p == 2) : (g - t == 3 && p == 3)))) {
                At[t] = a; Bt[t] = b;
            }
        }
    }

    // ---- Pass 2: reload x (L1 hit), FMA, plain store ----
    // asm volatile loads prevent CSE with pass-1 loads.
#pragma unroll
    for (int k = 0; k < 8; ++k) {
        const int pk = __popc(k);
        const float4* addr = xin + k * 8;
        float vx, vy, vz, vw;
        asm volatile("ld.global.nc.v4.f32 {%0,%1,%2,%3}, [%4];"
                     : "=f"(vx), "=f"(vy), "=f"(vz), "=f"(vw)
                     : "l"(addr));
        float4 o;
        o.x = fmaf(vx, At[pk + 0], Bt[pk + 0]);
        o.y = fmaf(vy, At[pk + 1], Bt[pk + 1]);
        o.z = fmaf(vz, At[pk + 1], Bt[pk + 1]);
        o.w = fmaf(vw, At[pk + 2], Bt[pk + 2]);
        xout[k * 8] = o;
    }
}

extern "C" void kernel_launch(void* const* d_in, const int* in_sizes, int n_in,
                              void* d_out, int out_size)
{
    const float* x      = (const float*)d_in[0];
    const float* weight = (const float*)d_in[1];
    const float* bias   = (const float*)d_in[2];
    float* out          = (float*)d_out;

    const int num_groups = in_sizes[0] / 1024;   // 4 MVs (1024 floats) per group

    // One group per warp, 16 warps per CTA -> num_groups/16 CTAs (~14 waves).
    const int threads = 512;
    int blocks = (num_groups + 15) / 16;
    clifford_ln_kernel<<<blocks, threads>>>(x, weight, bias, out, num_groups);
}

// round 13
// speedup vs baseline: 1.0609x; 1.0207x over previous
#include <cuda_runtime.h>
#include <cuda_bf16.h>

// CliffordLayerNorm — FINAL (R6 configuration, session-best wall 81.6us).
//
// Per 256-element multivector block: per-grade (popcount-of-index) mean/var
// normalization with affine weight[9]/bias[9]. Memory-bound at ~6.4TB/s
// (~80% DRAM active; actual DRAM traffic below the 536MB logical floor via
// L2 write merging) — at the HBM mixed read/write stream wall.
//
// Measured-optimal structure (12 rounds of single-variable search):
//  - 8 lanes per MV; warp covers ONE group of 4 MVs (4KB); no loop — CTA
//    exit lets the CLC pipeline the next CTA's load burst (beats grid-stride,
//    persistent, and blocked partitions).
//  - 256-thread CTAs (optimum of 128/256/512), occ 3, 8192 CTAs (~18 waves
//    of dynamic backfill absorbing per-SM spread).
//  - Pass 1 streams x into grade-relative sum/sumsq accumulators (values not
//    held -> low register pressure).
//  - 3-step shuffle-XOR "grade polynomial" butterfly merges relative grade
//    arrays (6->7->8->9) across the 8 lanes.
//  - var = E[x^2] - mean^2; affine collapsed to one FMA per element with
//    compile-time grade-offset coefficient selection.
//  - Pass 2 reloads x via ld.global.nc (L1-resident; beats smem stash and
//    register-held), applies FMA, plain store (beats __stcs).

#define NG 9
#define CEPS 1e-5f

__global__ void __launch_bounds__(256, 3)
clifford_ln_kernel(const float* __restrict__ x,
                   const float* __restrict__ weight,
                   const float* __restrict__ bias,
                   float* __restrict__ out,
                   int num_groups)   // groups of 1024 floats (4 MVs)
{
    const int lane = threadIdx.x & 31;
    const int grp = blockIdx.x * (blockDim.x >> 5) + (threadIdx.x >> 5);
    if (grp >= num_groups) return;

    const int sub = lane & 7;     // covers element bits 2,3,4
    const int mv  = lane >> 3;    // which of 4 MVs in the group
    const int p   = __popc(sub);  // relative grade base, 0..3

    // per-grade reciprocal counts C(8,g) = 1,8,28,56,70,56,28,8,1
    const float rc[NG] = {1.0f, 1.0f/8.0f, 1.0f/28.0f, 1.0f/56.0f, 1.0f/70.0f,
                          1.0f/56.0f, 1.0f/28.0f, 1.0f/8.0f, 1.0f};

    const float4* __restrict__ xin =
        reinterpret_cast<const float4*>(x) + (size_t)grp * 256 + mv * 64 + sub;
    float4* __restrict__ xout =
        reinterpret_cast<float4*>(out) + (size_t)grp * 256 + mv * 64 + sub;

    // ---- Pass 1: stream loads into grade-relative partial sums ----
    // t = popc(k)+popc(j) in 0..5.
    float S[NG], Q[NG];
#pragma unroll
    for (int t = 0; t < NG; ++t) { S[t] = 0.0f; Q[t] = 0.0f; }
#pragma unroll
    for (int k = 0; k < 8; ++k) {
        const int pk = __popc(k);          // compile-time after unroll
        const float4 v = xin[k * 8];
        S[pk + 0] += v.x;  Q[pk + 0] = fmaf(v.x, v.x, Q[pk + 0]);
        S[pk + 1] += v.y;  Q[pk + 1] = fmaf(v.y, v.y, Q[pk + 1]);
        S[pk + 1] += v.z;  Q[pk + 1] = fmaf(v.z, v.z, Q[pk + 1]);
        S[pk + 2] += v.w;  Q[pk + 2] = fmaf(v.w, v.w, Q[pk + 2]);
    }

    // ---- Butterfly merge over lane bits 0..2 (sub). 6 -> 7 -> 8 -> 9 ----
#pragma unroll
    for (int b = 0; b < 3; ++b) {
        const int n = 6 + b;               // current valid length
        const bool up = (sub >> b) & 1;
        float Sp[NG], Qp[NG];
#pragma unroll
        for (int t = 0; t < NG; ++t) {
            if (t < n) {
                Sp[t] = __shfl_xor_sync(0xffffffffu, S[t], 1 << b);
                Qp[t] = __shfl_xor_sync(0xffffffffu, Q[t], 1 << b);
            }
        }
        float Sn[NG], Qn[NG];
#pragma unroll
        for (int t = 0; t < NG; ++t) {
            if (t <= n) {
                float lo_s = (t < n) ? (up ? Sp[t] : S[t]) : 0.0f;
                float hi_s = (t > 0) ? (up ? S[t - 1] : Sp[t - 1]) : 0.0f;
                Sn[t] = lo_s + hi_s;
                float lo_q = (t < n) ? (up ? Qp[t] : Q[t]) : 0.0f;
                float hi_q = (t > 0) ? (up ? Q[t - 1] : Qp[t - 1]) : 0.0f;
                Qn[t] = lo_q + hi_q;
            }
        }
#pragma unroll
        for (int t = 0; t < NG; ++t) {
            if (t <= n) { S[t] = Sn[t]; Q[t] = Qn[t]; }
        }
    }

    // ---- Per-grade affine coefficients; compress to this lane's 6 ----
    float At[6], Bt[6];
#pragma unroll
    for (int g = 0; g < NG; ++g) {
        float m   = S[g] * rc[g];
        float var = fmaf(Q[g], rc[g], -m * m);
        float inv = rsqrtf(var + CEPS);
        float a   = inv * __ldg(weight + g);
        float b   = fmaf(-m, a, __ldg(bias + g));
        // lane needs grades p..p+5 -> slot t = g - p
#pragma unroll
        for (int t = 0; t < 6; ++t) {
            if (g - t == 0 ? (p == 0) : (g - t == 1 ? (p == 1) :
                (g - t == 2 ? (p == 2) : (g - t == 3 && p == 3)))) {
                At[t] = a; Bt[t] = b;
            }
        }
    }

    // ---- Pass 2: reload x (L1 hit), FMA, plain store ----
    // asm volatile loads prevent CSE with pass-1 loads.
#pragma unroll
    for (int k = 0; k < 8; ++k) {
        const int pk = __popc(k);
        const float4* addr = xin + k * 8;
        float vx, vy, vz, vw;
        asm volatile("ld.global.nc.v4.f32 {%0,%1,%2,%3}, [%4];"
                     : "=f"(vx), "=f"(vy), "=f"(vz), "=f"(vw)
                     : "l"(addr));
        float4 o;
        o.x = fmaf(vx, At[pk + 0], Bt[pk + 0]);
        o.y = fmaf(vy, At[pk + 1], Bt[pk + 1]);
        o.z = fmaf(vz, At[pk + 1], Bt[pk + 1]);
        o.w = fmaf(vw, At[pk + 2], Bt[pk + 2]);
        xout[k * 8] = o;
    }
}

extern "C" void kernel_launch(void* const* d_in, const int* in_sizes, int n_in,
                              void* d_out, int out_size)
{
    const float* x      = (const float*)d_in[0];
    const float* weight = (const float*)d_in[1];
    const float* bias   = (const float*)d_in[2];
    float* out          = (float*)d_out;

    const int num_groups = in_sizes[0] / 1024;   // 4 MVs (1024 floats) per group

    // One group per warp, 8 warps per CTA -> num_groups/8 CTAs (~18 waves).
    const int threads = 256;
    int blocks = (num_groups + 7) / 8;
    clifford_ln_kernel<<<blocks, threads>>>(x, weight, bias, out, num_groups);
}